// round 2
// baseline (speedup 1.0000x reference)
#include <cuda_runtime.h>
#include <cstddef>

#define NB   4
#define TSZ  16
#define SRr  4
#define PD   1
#define SSn  11     // search span = 2*(SR+PADD)+1
#define SSC  9      // cropped span = 2*SR+1
#define WINs 26     // T + 2*(SR+PADD)
#define SWt  0.1f

// ---------------- scratch (device globals; no allocation) ----------------
__device__ float g_W6[36];                       // fused blur+pool 6x6 weights
__device__ float g_ps1[NB*256*256], g_pd1[NB*256*256];
__device__ float g_ps2[NB*128*128], g_pd2[NB*128*128];
__device__ float g_ps3[NB*64*64],   g_pd3[NB*64*64];
__device__ float g_offA[NB*16*16*2];
__device__ float g_offB[NB*16*16*2];

// ---------------- init: gaussian kernel -> fused 6x6 pool weights --------
__global__ void init_weights_kernel() {
    float g[5];
    for (int i = 0; i < 5; i++) { float ax = (float)i - 2.0f; g[i] = expf(-ax*ax*0.5f); }
    float k[5][5]; float s = 0.f;
    for (int i = 0; i < 5; i++) for (int j = 0; j < 5; j++) { k[i][j] = g[i]*g[j]; s += k[i][j]; }
    for (int i = 0; i < 5; i++) for (int j = 0; j < 5; j++) k[i][j] /= s;
    // out[i,j] = 0.25 * sum_{a,b in {0,1}} blur(2i+a, 2j+b); blur has zero pad=2
    for (int u = 0; u < 6; u++) for (int v = 0; v < 6; v++) {
        float w = 0.f;
        for (int a = 0; a < 2; a++) for (int b = 0; b < 2; b++) {
            int p = u - a, q = v - b;
            if (p >= 0 && p < 5 && q >= 0 && q < 5) w += k[p][q];
        }
        g_W6[u*6 + v] = 0.25f * w;
    }
}

// ---------------- pyramid downsample (blur 5x5 zero-pad + avgpool 2) -----
// processes src and dst images together: img 0..3 = src batches, 4..7 = dst
__global__ void down_kernel(const float* __restrict__ in_s, const float* __restrict__ in_d,
                            float* __restrict__ out_s, float* __restrict__ out_d, int H)
{
    int Ho = H >> 1;
    int idx = blockIdx.x * blockDim.x + threadIdx.x;
    int total = 2 * NB * Ho * Ho;
    if (idx >= total) return;
    int x   = idx % Ho;
    int y   = (idx / Ho) % Ho;
    int img = idx / (Ho * Ho);
    const float* in  = (img < NB) ? (in_s  + (size_t)img      * H  * H)
                                  : (in_d  + (size_t)(img-NB) * H  * H);
    float*       out = (img < NB) ? (out_s + (size_t)img      * Ho * Ho)
                                  : (out_d + (size_t)(img-NB) * Ho * Ho);
    int by = 2*y - 2, bx = 2*x - 2;
    float acc = 0.f;
    #pragma unroll
    for (int u = 0; u < 6; u++) {
        int yy = by + u;
        if (yy < 0 || yy >= H) continue;
        const float* row = in + (size_t)yy * H;
        #pragma unroll
        for (int v = 0; v < 6; v++) {
            int xx = bx + v;
            if (xx < 0 || xx >= H) continue;
            acc = fmaf(g_W6[u*6 + v], row[xx], acc);
        }
    }
    out[(size_t)y * Ho + x] = acc;
}

// ---------------- one alignment level: block = one tile -------------------
__global__ void __launch_bounds__(256, 8)
step_kernel(const float* __restrict__ src, const float* __restrict__ dst,
            int H, int nth,
            const float* __restrict__ prev_off, int pnth,
            float* __restrict__ out_off,     // per-tile (non-final), else null
            float* __restrict__ out_pix)     // final pixel maps (d_out), else null
{
    const int W = H, ntw = nth, pntw = pnth;
    int tile = blockIdx.x;
    int tx = tile % ntw;
    int t2 = tile / ntw;
    int ty = t2 % nth;
    int nb = t2 / nth;
    int tid = threadIdx.x;

    __shared__ float s_src[TSZ*TSZ];
    __shared__ float s_win[WINs*(WINs+1)];
    __shared__ float s_dist[SSn*SSn];
    __shared__ float s_init[2];
    __shared__ float s_res[3];

    // ---- inherit init offset (matches _inherit: x2, clip, round-half-even)
    if (tid == 0) {
        float iyf = 0.f, ixf = 0.f;
        if (prev_off) {
            const float* p = prev_off + ((size_t)((nb*pnth + (ty>>1))*pntw + (tx>>1)))*2;
            float iy = (float)(ty*TSZ), ix = (float)(tx*TSZ);
            iyf = rintf(fminf(fmaxf(2.f*p[0] + iy, 0.f), (float)(H-TSZ)) - iy);
            ixf = rintf(fminf(fmaxf(2.f*p[1] + ix, 0.f), (float)(W-TSZ)) - ix);
        }
        s_init[0] = iyf; s_init[1] = ixf;
    }
    __syncthreads();
    const int oy = (int)s_init[0];
    const int ox = (int)s_init[1];

    const float* simg = src + (size_t)nb * H * W;
    const float* dimg = dst + (size_t)nb * H * W;

    // ---- load src tile (16x16, one elem/thread)
    {
        int i = tid >> 4, j = tid & 15;
        s_src[tid] = simg[(size_t)(ty*TSZ + i) * W + tx*TSZ + j];
    }

    // ---- load 26x26 dst window with clamped gather
    int y0 = ty*TSZ + oy - (SRr + PD);
    int x0 = tx*TSZ + ox - (SRr + PD);
    for (int idx = tid; idx < WINs*WINs; idx += 256) {
        int r = idx / WINs, c = idx % WINs;
        int yy = min(max(y0 + r, 0), H - 1);
        int xx = min(max(x0 + c, 0), W - 1);
        s_win[r*(WINs+1) + c] = dimg[(size_t)yy * W + xx];
    }
    __syncthreads();

    // ---- 121 candidates: MSE over 16x16 + spatial penalty
    if (tid < SSn*SSn) {
        int sy = tid / SSn, sx = tid % SSn;
        float sum = 0.f;
        for (int i = 0; i < TSZ; i++) {
            const float* wr = s_win + (sy + i)*(WINs+1) + sx;
            const float* sr = s_src + i*TSZ;
            #pragma unroll
            for (int j = 0; j < TSZ; j++) {
                float d = wr[j] - sr[j];
                sum = fmaf(d, d, sum);
            }
        }
        float ay = ((float)sy - (float)(SRr+PD)) / (float)SSn;
        float ax = ((float)sx - (float)(SRr+PD)) / (float)SSn;
        s_dist[tid] = sum * (1.0f/256.0f) + SWt * (ay*ay + ax*ax);
    }
    __syncthreads();

    // ---- argmin (first-index tie-break, matching jnp.argmin) + subpixel
    if (tid == 0) {
        float best = 3.4e38f; int bk = 0;
        for (int k2 = 0; k2 < SSC*SSC; k2++) {
            int py = k2 / SSC, px = k2 % SSC;
            float v = s_dist[(py+PD)*SSn + px + PD];
            if (v < best) { best = v; bk = k2; }
        }
        int py = bk / SSC, px = bk % SSC;
        float r[9];
        #pragma unroll
        for (int dy = 0; dy < 3; dy++)
            #pragma unroll
            for (int dx = 0; dx < 3; dx++)
                r[dy*3+dx] = s_dist[(py+PD-1+dy)*SSn + (px+PD-1+dx)];

        float a11 = (  r[0]-2.f*r[1]+r[2] + 2.f*r[3]-4.f*r[4]+2.f*r[5] +   r[6]-2.f*r[7]+r[8]) * 0.25f;
        float a22 = (  r[0]+2.f*r[1]+r[2] - 2.f*r[3]-4.f*r[4]-2.f*r[5] +   r[6]+2.f*r[7]+r[8]) * 0.25f;
        float a12 = (  r[0]        -r[2]                               -   r[6]         +r[8]) * 0.25f;
        float b1  = ( -r[0]        +r[2] - 2.f*r[3]        +2.f*r[5]   -   r[6]         +r[8]) * 0.125f;
        float b2  = ( -r[0]-2.f*r[1]-r[2]                              +   r[6]+2.f*r[7]+r[8]) * 0.125f;
        a11 = fmaxf(a11, 0.f);
        a22 = fmaxf(a22, 0.f);
        float det  = a11*a22 - a12*a12;
        float a12z = (det < 0.f) ? 0.f : a12;
        float mux  = -(a22*b1 - a12z*b2) / det;
        float muy  = -(a11*b2 - a12z*b1) / det;
        float mlen = sqrtf(muy*muy + mux*mux);
        float dxs  = (mlen < 1.f) ? mux : 0.f;   // NaN/Inf -> 0, matches jnp.where
        float dys  = (mlen < 1.f) ? muy : 0.f;

        float offy = s_init[0] + (float)(py - SRr) + dys;
        float offx = s_init[1] + (float)(px - SRr) + dxs;
        if (out_off) { out_off[(size_t)tile*2 + 0] = offy; out_off[(size_t)tile*2 + 1] = offx; }
        s_res[0] = offy; s_res[1] = offx; s_res[2] = best;
    }
    __syncthreads();

    // ---- final level: replicate tile result to 16x16 pixel maps
    if (out_pix) {
        int i = tid >> 4, j = tid & 15;
        int y = ty*TSZ + i, x = tx*TSZ + j;
        size_t pix = ((size_t)nb * H + y) * W + x;
        out_pix[pix*2 + 0] = s_res[0];
        out_pix[pix*2 + 1] = s_res[1];
        out_pix[(size_t)NB * H * W * 2 + pix] = s_res[2];
    }
}

// ---------------- launch ---------------------------------------------------
extern "C" void kernel_launch(void* const* d_in, const int* in_sizes, int n_in,
                              void* d_out, int out_size)
{
    const float* src = (const float*)d_in[0];
    const float* dst = (const float*)d_in[1];
    float* out = (float*)d_out;

    float *ps1, *pd1, *ps2, *pd2, *ps3, *pd3, *offA, *offB;
    cudaGetSymbolAddress((void**)&ps1,  g_ps1);
    cudaGetSymbolAddress((void**)&pd1,  g_pd1);
    cudaGetSymbolAddress((void**)&ps2,  g_ps2);
    cudaGetSymbolAddress((void**)&pd2,  g_pd2);
    cudaGetSymbolAddress((void**)&ps3,  g_ps3);
    cudaGetSymbolAddress((void**)&pd3,  g_pd3);
    cudaGetSymbolAddress((void**)&offA, g_offA);
    cudaGetSymbolAddress((void**)&offB, g_offB);

    init_weights_kernel<<<1, 1>>>();

    // pyramid: 512 -> 256 -> 128 -> 64 (src + dst fused per launch)
    {
        int H = 512, Ho = 256, total = 2*NB*Ho*Ho;
        down_kernel<<<(total + 255)/256, 256>>>(src, dst, ps1, pd1, H);
    }
    {
        int H = 256, Ho = 128, total = 2*NB*Ho*Ho;
        down_kernel<<<(total + 255)/256, 256>>>(ps1, pd1, ps2, pd2, H);
    }
    {
        int H = 128, Ho = 64, total = 2*NB*Ho*Ho;
        down_kernel<<<(total + 255)/256, 256>>>(ps2, pd2, ps3, pd3, H);
    }

    // coarse -> fine alignment
    step_kernel<<<NB*4*4,   256>>>(ps3, pd3,  64,  4, nullptr, 0,  offA, nullptr);
    step_kernel<<<NB*8*8,   256>>>(ps2, pd2, 128,  8, offA,    4,  offB, nullptr);
    step_kernel<<<NB*16*16, 256>>>(ps1, pd1, 256, 16, offB,    8,  offA, nullptr);
    step_kernel<<<NB*32*32, 256>>>(src, dst, 512, 32, offA,   16,  nullptr, out);
}